// round 16
// baseline (speedup 1.0000x reference)
#include <cuda_runtime.h>
#include <cstdint>

#define B_ 4
#define S_ 2048
#define H_ 8
#define D_ 64
#define C_ 64
#define NC_ (S_/C_)      // 32
#define BH_ (B_*H_)      // 32
#define SCALE 0.125f
#define KTS 66           // k1 kT stride
#define VTS 72           // v/state stride: B-load banks 8tq+g -> conflict-free
#define QS_ 68           // q/k/scores stride: A-load banks 4g+tq -> conflict-free

// Per-(bh,chunk) 64x64 state scratch, state[d][e]: 16 MB
__device__ float g_state[(size_t)BH_*NC_*D_*D_];

__device__ __forceinline__ float featf(float x) {
    return x > 0.f ? x + 1.f : __expf(x);   // elu(x)+1
}
__device__ __forceinline__ uint32_t tf32r(float x) {
    uint32_t r; asm("cvt.rn.tf32.f32 %0, %1;" : "=r"(r) : "f"(x)); return r;
}
__device__ __forceinline__ uint32_t smem_u32(const void* p) {
    uint32_t a; asm("{ .reg .u64 t; cvta.to.shared.u64 t, %1; cvt.u32.u64 %0, t; }"
                    : "=r"(a) : "l"(p));
    return a;
}
__device__ __forceinline__ void cp16(uint32_t dst, const void* src) {
    asm volatile("cp.async.ca.shared.global [%0], [%1], 16;" :: "r"(dst), "l"(src));
}
#define CP_COMMIT() asm volatile("cp.async.commit_group;" ::: "memory")
#define CP_WAIT(n)  asm volatile("cp.async.wait_group %0;" :: "n"(n) : "memory")

// D(16x8,f32) += A(16x8,tf32) @ B(8x8,tf32)   [m16n8k8 row.col]
#define MMA8(D, A0, A1, A2, A3, B0, B1)                                      \
    asm volatile("mma.sync.aligned.m16n8k8.row.col.f32.tf32.tf32.f32 "       \
        "{%0,%1,%2,%3}, {%4,%5,%6,%7}, {%8,%9}, {%0,%1,%2,%3};"              \
        : "+f"((D)[0]), "+f"((D)[1]), "+f"((D)[2]), "+f"((D)[3])             \
        : "r"(A0), "r"(A1), "r"(A2), "r"(A3), "r"(B0), "r"(B1))

// Convert OWN cp.async'd 16B chunks in place (post-wait, pre-barrier: the
// thread reads only addresses it wrote itself -> no extra sync needed).
#define CVT_OWN_V(VPTR, T, STRIDE)                                           \
    do {                                                                      \
        _Pragma("unroll")                                                     \
        for (int _r = 0; _r < 4; _r++) {                                      \
            int _idx = (T) + _r * 256;                                        \
            int _row = _idx >> 4;                                             \
            int _d4  = (_idx & 15) << 2;                                      \
            float4* _p = reinterpret_cast<float4*>((VPTR) + _row * (STRIDE) + _d4); \
            float4 _f = *_p;                                                  \
            uint4 _u = make_uint4(tf32r(_f.x), tf32r(_f.y),                   \
                                  tf32r(_f.z), tf32r(_f.w));                  \
            *reinterpret_cast<uint4*>(_p) = _u;                               \
        }                                                                     \
    } while (0)

// ---------------------------------------------------------------------------
// Kernel 1: state[d][e] = sum_j (k[j][d]*SCALE) * v[j][e]
// [R15 + own-region post-wait v conversion; mainloop reads bits]
// ---------------------------------------------------------------------------
__global__ void __launch_bounds__(256) k_chunk_sum(const float* __restrict__ qk,
                                                   const float* __restrict__ v) {
    extern __shared__ float sm[];
    float* kT = sm;                  // [64][KTS] kT[d][j] (tf32 bits)
    float* vS = kT + 64 * KTS;       // [64][VTS] v[j][e]  (tf32 bits after cvt)
    uint32_t* kTu = reinterpret_cast<uint32_t*>(kT);
    uint32_t* vSu = reinterpret_cast<uint32_t*>(vS);
    const uint32_t smb = smem_u32(sm);

    const int t  = threadIdx.x;
    const int bh = blockIdx.x / NC_;
    const int c  = blockIdx.x % NC_;
    const int b  = bh / H_, h = bh % H_;
    const int s0 = c * C_;

    #pragma unroll
    for (int r = 0; r < 4; r++) {
        int idx = t + r * 256;
        int j   = idx >> 4;
        int d4  = (idx & 15) << 2;
        cp16(smb + (uint32_t)(64 * KTS + j * VTS + d4) * 4,
             v + (((size_t)b * S_ + s0 + j) * H_ + h) * D_ + d4);
    }
    CP_COMMIT();

    #pragma unroll
    for (int r = 0; r < 4; r++) {
        int idx = t + r * 256;
        int j   = idx >> 4;
        int d4  = (idx & 15) << 2;
        const float4 kf = *reinterpret_cast<const float4*>(
            qk + ((((size_t)b * S_ + s0 + j) * 2 + 1) * H_ + h) * D_ + d4);
        kTu[(d4 + 0) * KTS + j] = tf32r(featf(kf.x) * SCALE);
        kTu[(d4 + 1) * KTS + j] = tf32r(featf(kf.y) * SCALE);
        kTu[(d4 + 2) * KTS + j] = tf32r(featf(kf.z) * SCALE);
        kTu[(d4 + 3) * KTS + j] = tf32r(featf(kf.w) * SCALE);
    }
    CP_WAIT(0);
    CVT_OWN_V(vS, t, VTS);    // own chunks only: no barrier needed before this
    __syncthreads();

    const int warp = t >> 5, lane = t & 31;
    const int g = lane >> 2, tq = lane & 3;
    const int d0w = (warp >> 1) * 16;
    const int eh  = warp & 1;

    float acc[4][4];
    #pragma unroll
    for (int n = 0; n < 4; n++)
        #pragma unroll
        for (int p = 0; p < 4; p++) acc[n][p] = 0.f;

    #pragma unroll
    for (int kt = 0; kt < 8; kt++) {
        const int j0 = kt * 8;
        uint32_t a0 = kTu[(d0w + g)     * KTS + j0 + tq];
        uint32_t a1 = kTu[(d0w + g + 8) * KTS + j0 + tq];
        uint32_t a2 = kTu[(d0w + g)     * KTS + j0 + tq + 4];
        uint32_t a3 = kTu[(d0w + g + 8) * KTS + j0 + tq + 4];
        #pragma unroll
        for (int nt = 0; nt < 4; nt++) {
            const int e0 = (eh * 4 + nt) * 8;
            uint32_t b0 = vSu[(j0 + tq)     * VTS + e0 + g];   // pre-rounded bits
            uint32_t b1 = vSu[(j0 + tq + 4) * VTS + e0 + g];
            MMA8(acc[nt], a0, a1, a2, a3, b0, b1);
        }
    }

    float* base = g_state + (size_t)(bh * NC_ + c) * (D_ * D_);
    #pragma unroll
    for (int nt = 0; nt < 4; nt++) {
        const int e = (eh * 4 + nt) * 8 + 2 * tq;
        *reinterpret_cast<float2*>(base + (d0w + g)     * D_ + e) =
            make_float2(acc[nt][0], acc[nt][1]);
        *reinterpret_cast<float2*>(base + (d0w + g + 8) * D_ + e) =
            make_float2(acc[nt][2], acc[nt][3]);
    }
}

// ---------------------------------------------------------------------------
// Kernel 2: exclusive prefix over chunks (float4/thread).
// Accumulates in f32; stores RN tf32-rounded bits.  [R15 verbatim]
// ---------------------------------------------------------------------------
__global__ void __launch_bounds__(256) k_prefix() {
    const int el  = blockIdx.x * 256 + threadIdx.x;   // float4 index
    const int bh  = el >> 10;
    const int off = (el & 1023) << 2;
    float* p = g_state + (size_t)bh * NC_ * (D_ * D_) + off;
    float4 run = make_float4(0.f, 0.f, 0.f, 0.f);
    #pragma unroll
    for (int c = 0; c < NC_; c++) {
        float4* q4 = reinterpret_cast<float4*>(p + (size_t)c * (D_ * D_));
        float4 tmp = *q4;
        float4 outq;
        outq.x = __uint_as_float(tf32r(run.x));
        outq.y = __uint_as_float(tf32r(run.y));
        outq.z = __uint_as_float(tf32r(run.z));
        outq.w = __uint_as_float(tf32r(run.w));
        *q4 = outq;
        run.x += tmp.x; run.y += tmp.y; run.z += tmp.z; run.w += tmp.w;
    }
}

// ---------------------------------------------------------------------------
// Kernel 3: out[i][e] = norm_i * ( q@state + causal(q@k^T) @ v )
// [R15 + own-region post-wait v conversion; phase-2 reads bits]
// ---------------------------------------------------------------------------
__global__ void __launch_bounds__(256) k_output(const float* __restrict__ qk,
                                                const float* __restrict__ v,
                                                const float* __restrict__ nvec,
                                                const float* __restrict__ offset,
                                                float* __restrict__ out) {
    extern __shared__ float sm[];
    float* qS  = sm;                 // [64][QS_] q (tf32 bits)
    float* kS  = qS + 64 * QS_;      // [64][QS_] k; later scores (stride QS_)
    float* vS  = kS + 64 * QS_;      // [64][VTS] tf32 bits after cvt
    float* stS = vS + 64 * VTS;      // [64][VTS] tf32 bits (pre-rounded)
    float* sS  = kS;                 // scores alias kS
    uint32_t* qSu  = reinterpret_cast<uint32_t*>(qS);
    uint32_t* kSu  = reinterpret_cast<uint32_t*>(kS);
    uint32_t* vSu  = reinterpret_cast<uint32_t*>(vS);
    uint32_t* stSu = reinterpret_cast<uint32_t*>(stS);
    uint32_t* sSu  = reinterpret_cast<uint32_t*>(sS);
    const uint32_t smb = smem_u32(sm);

    const int t  = threadIdx.x;
    const int bh = blockIdx.x / NC_;
    const int c  = blockIdx.x % NC_;
    const int b  = bh / H_, h = bh % H_;
    const int s0 = c * C_;

    const float* stg = g_state + (size_t)(bh * NC_ + c) * (D_ * D_);

    const uint32_t vOff  = (uint32_t)(2 * 64 * QS_);
    const uint32_t stOff = (uint32_t)(2 * 64 * QS_ + 64 * VTS);

    // group 0: state; group 1: v
    #pragma unroll
    for (int r = 0; r < 4; r++) {
        int idx = t + r * 256;
        int row = idx >> 4;
        int d4  = (idx & 15) << 2;
        cp16(smb + (stOff + (uint32_t)(row * VTS + d4)) * 4, stg + row * D_ + d4);
    }
    CP_COMMIT();
    #pragma unroll
    for (int r = 0; r < 4; r++) {
        int idx = t + r * 256;
        int row = idx >> 4;
        int d4  = (idx & 15) << 2;
        cp16(smb + (vOff + (uint32_t)(row * VTS + d4)) * 4,
             v + (((size_t)b * S_ + s0 + row) * H_ + h) * D_ + d4);
    }
    CP_COMMIT();

    // q,k: batch ALL global loads first (MLP=8), then transform+store
    float4 qf[4], kf[4];
    #pragma unroll
    for (int r = 0; r < 4; r++) {
        int idx = t + r * 256;
        int row = idx >> 4;
        int d4  = (idx & 15) << 2;
        size_t s = (size_t)(s0 + row);
        qf[r] = *reinterpret_cast<const float4*>(
            qk + ((((size_t)b * S_ + s) * 2 + 0) * H_ + h) * D_ + d4);
        kf[r] = *reinterpret_cast<const float4*>(
            qk + ((((size_t)b * S_ + s) * 2 + 1) * H_ + h) * D_ + d4);
    }
    #pragma unroll
    for (int r = 0; r < 4; r++) {
        int idx = t + r * 256;
        int row = idx >> 4;
        int d4  = (idx & 15) << 2;
        uint4 qu = make_uint4(tf32r(featf(qf[r].x)), tf32r(featf(qf[r].y)),
                              tf32r(featf(qf[r].z)), tf32r(featf(qf[r].w)));
        *reinterpret_cast<uint4*>(&qSu[row * QS_ + d4]) = qu;
        uint4 ku = make_uint4(tf32r(featf(kf[r].x) * SCALE), tf32r(featf(kf[r].y) * SCALE),
                              tf32r(featf(kf[r].z) * SCALE), tf32r(featf(kf[r].w) * SCALE));
        *reinterpret_cast<uint4*>(&kSu[row * QS_ + d4]) = ku;
    }

    const int warp = t >> 5, lane = t & 31;
    const int g = lane >> 2, tq = lane & 3;
    const int ib = warp >> 1;
    const int eh = warp & 1;
    const int i0 = ib * 16;
    const int ntS = 2 * ib + 2;      // causal j-tiles for this i-block

    const float offh = offset[h];
    const int iA = i0 + g, iB = i0 + g + 8;
    float zA = nvec[((size_t)b * S_ + s0 + iA) * H_ + h] + offh;
    float zB = nvec[((size_t)b * S_ + s0 + iB) * H_ + h] + offh;

    CP_WAIT(0);               // state + v landed
    CVT_OWN_V(vS, t, VTS);    // own chunks only: pre-barrier safe
    __syncthreads();

    float dO[4][4];
    float dS[4][4];
    #pragma unroll
    for (int n = 0; n < 4; n++)
        #pragma unroll
        for (int p = 0; p < 4; p++) { dO[n][p] = 0.f; dS[n][p] = 0.f; }

    // Phase 1: out1 = q @ state (own e-tiles); scores = q @ k^T (parity j-tiles)
    #pragma unroll
    for (int kt = 0; kt < 8; kt++) {
        const int d0 = kt * 8;
        uint32_t a0 = qSu[(i0 + g)     * QS_ + d0 + tq];
        uint32_t a1 = qSu[(i0 + g + 8) * QS_ + d0 + tq];
        uint32_t a2 = qSu[(i0 + g)     * QS_ + d0 + tq + 4];
        uint32_t a3 = qSu[(i0 + g + 8) * QS_ + d0 + tq + 4];
        #pragma unroll
        for (int nt = 0; nt < 4; nt++) {
            const int e0 = (eh * 4 + nt) * 8;
            uint32_t b0 = stSu[(d0 + tq)     * VTS + e0 + g];   // pre-rounded bits
            uint32_t b1 = stSu[(d0 + tq + 4) * VTS + e0 + g];
            MMA8(dO[nt], a0, a1, a2, a3, b0, b1);
        }
        #pragma unroll
        for (int nt2 = 0; nt2 < 4; nt2++) {
            const int jt = 2 * nt2 + eh;
            if (jt >= ntS) break;
            const int j0 = jt * 8;
            uint32_t b0 = kSu[(j0 + g) * QS_ + d0 + tq];
            uint32_t b1 = kSu[(j0 + g) * QS_ + d0 + tq + 4];
            MMA8(dS[nt2], a0, a1, a2, a3, b0, b1);
        }
    }

    __syncthreads();           // all reads of kS done; scores may overwrite it

    // Causal mask + store parity score tiles (stride QS_, alias kS)
    #pragma unroll
    for (int nt2 = 0; nt2 < 4; nt2++) {
        const int jt = 2 * nt2 + eh;
        if (jt >= ntS) break;
        const int j = jt * 8 + 2 * tq;
        sSu[iA * QS_ + j]     = tf32r((j     <= iA) ? dS[nt2][0] : 0.f);
        sSu[iA * QS_ + j + 1] = tf32r((j + 1 <= iA) ? dS[nt2][1] : 0.f);
        sSu[iB * QS_ + j]     = tf32r((j     <= iB) ? dS[nt2][2] : 0.f);
        sSu[iB * QS_ + j + 1] = tf32r((j + 1 <= iB) ? dS[nt2][3] : 0.f);
    }
    __syncthreads();           // scores visible to all

    // Phase 2: out += scores @ v (all causal j-tiles, own e-tiles)
    #pragma unroll
    for (int kt = 0; kt < 8; kt++) {
        if (kt >= ntS) break;
        const int j0 = kt * 8;
        uint32_t a0 = sSu[(i0 + g)     * QS_ + j0 + tq];
        uint32_t a1 = sSu[(i0 + g + 8) * QS_ + j0 + tq];
        uint32_t a2 = sSu[(i0 + g)     * QS_ + j0 + tq + 4];
        uint32_t a3 = sSu[(i0 + g + 8) * QS_ + j0 + tq + 4];
        #pragma unroll
        for (int nt = 0; nt < 4; nt++) {
            const int e0 = (eh * 4 + nt) * 8;
            uint32_t b0 = vSu[(j0 + tq)     * VTS + e0 + g];   // pre-rounded bits
            uint32_t b1 = vSu[(j0 + tq + 4) * VTS + e0 + g];
            MMA8(dO[nt], a0, a1, a2, a3, b0, b1);
        }
    }

    // Epilogue: norm scale + direct fragment stores (float2, full sectors)
    float nA = 1.f / (1.f + __expf(zA));
    float nB = 1.f / (1.f + __expf(zB));
    float* opA = out + (((size_t)b * S_ + s0 + iA) * H_ + h) * D_;
    float* opB = out + (((size_t)b * S_ + s0 + iB) * H_ + h) * D_;
    #pragma unroll
    for (int nt = 0; nt < 4; nt++) {
        const int e = (eh * 4 + nt) * 8 + 2 * tq;
        *reinterpret_cast<float2*>(opA + e) =
            make_float2(dO[nt][0] * nA, dO[nt][1] * nA);
        *reinterpret_cast<float2*>(opB + e) =
            make_float2(dO[nt][2] * nB, dO[nt][3] * nB);
    }
}

// ---------------------------------------------------------------------------
extern "C" void kernel_launch(void* const* d_in, const int* in_sizes, int n_in,
                              void* d_out, int out_size) {
    (void)in_sizes; (void)n_in; (void)out_size;
    const float* qk     = (const float*)d_in[0];
    const float* v      = (const float*)d_in[1];
    const float* nvec   = (const float*)d_in[2];
    const float* offset = (const float*)d_in[3];
    float* out = (float*)d_out;

    const int smem1 = (64 * KTS + 64 * VTS) * (int)sizeof(float);          // 35328
    const int smem3 = (2 * 64 * QS_ + 2 * 64 * VTS) * (int)sizeof(float);  // 71680
    cudaFuncSetAttribute(k_chunk_sum, cudaFuncAttributeMaxDynamicSharedMemorySize, smem1);
    cudaFuncSetAttribute(k_output,    cudaFuncAttributeMaxDynamicSharedMemorySize, smem3);

    k_chunk_sum<<<BH_ * NC_, 256, smem1>>>(qk, v);
    k_prefix<<<128, 256>>>();
    k_output<<<BH_ * NC_, 256, smem3>>>(qk, v, nvec, offset, out);
}

// round 17
// speedup vs baseline: 1.1176x; 1.1176x over previous
#include <cuda_runtime.h>
#include <cstdint>

#define B_ 4
#define S_ 2048
#define H_ 8
#define D_ 64
#define C_ 64
#define NC_ (S_/C_)      // 32
#define BH_ (B_*H_)      // 32
#define SCALE 0.125f
#define VTS 72           // v/state/k1-k stride: conflict-free B-loads AND A-gathers
#define QS_ 68           // q/k/scores stride (k3): A-load banks 4g+tq -> conflict-free

// Per-(bh,chunk) 64x64 state scratch, state[d][e]: 16 MB
__device__ float g_state[(size_t)BH_*NC_*D_*D_];

__device__ __forceinline__ float featf(float x) {
    return x > 0.f ? x + 1.f : __expf(x);   // elu(x)+1
}
__device__ __forceinline__ uint32_t tf32r(float x) {
    uint32_t r; asm("cvt.rn.tf32.f32 %0, %1;" : "=r"(r) : "f"(x)); return r;
}
__device__ __forceinline__ uint32_t smem_u32(const void* p) {
    uint32_t a; asm("{ .reg .u64 t; cvta.to.shared.u64 t, %1; cvt.u32.u64 %0, t; }"
                    : "=r"(a) : "l"(p));
    return a;
}
__device__ __forceinline__ void cp16(uint32_t dst, const void* src) {
    asm volatile("cp.async.ca.shared.global [%0], [%1], 16;" :: "r"(dst), "l"(src));
}
#define CP_COMMIT() asm volatile("cp.async.commit_group;" ::: "memory")
#define CP_WAIT(n)  asm volatile("cp.async.wait_group %0;" :: "n"(n) : "memory")

// D(16x8,f32) += A(16x8,tf32) @ B(8x8,tf32)   [m16n8k8 row.col]
#define MMA8(D, A0, A1, A2, A3, B0, B1)                                      \
    asm volatile("mma.sync.aligned.m16n8k8.row.col.f32.tf32.tf32.f32 "       \
        "{%0,%1,%2,%3}, {%4,%5,%6,%7}, {%8,%9}, {%0,%1,%2,%3};"              \
        : "+f"((D)[0]), "+f"((D)[1]), "+f"((D)[2]), "+f"((D)[3])             \
        : "r"(A0), "r"(A1), "r"(A2), "r"(A3), "r"(B0), "r"(B1))

// ---------------------------------------------------------------------------
// Kernel 1: state[d][e] = sum_j (k[j][d]*SCALE) * v[j][e]
// k stored NATURALLY [j][d] (vectorized STS, stride 72); A-fragments of k^T
// gathered directly from natural layout -> conflict-free (banks 8tq+g).
// No transpose transform. v via cp.async + inline RN cvt (hidden in mainloop).
// ---------------------------------------------------------------------------
__global__ void __launch_bounds__(256) k_chunk_sum(const float* __restrict__ qk,
                                                   const float* __restrict__ v) {
    extern __shared__ float sm[];
    float* kS = sm;                  // [64][VTS] k[j][d] (tf32 bits)
    float* vS = kS + 64 * VTS;       // [64][VTS] v[j][e] (raw f32)
    uint32_t* kSu = reinterpret_cast<uint32_t*>(kS);
    const uint32_t smb = smem_u32(sm);

    const int t  = threadIdx.x;
    const int bh = blockIdx.x / NC_;
    const int c  = blockIdx.x % NC_;
    const int b  = bh / H_, h = bh % H_;
    const int s0 = c * C_;

    #pragma unroll
    for (int r = 0; r < 4; r++) {
        int idx = t + r * 256;
        int j   = idx >> 4;
        int d4  = (idx & 15) << 2;
        cp16(smb + (uint32_t)(64 * VTS + j * VTS + d4) * 4,
             v + (((size_t)b * S_ + s0 + j) * H_ + h) * D_ + d4);
    }
    CP_COMMIT();

    #pragma unroll
    for (int r = 0; r < 4; r++) {
        int idx = t + r * 256;
        int j   = idx >> 4;
        int d4  = (idx & 15) << 2;
        const float4 kf = *reinterpret_cast<const float4*>(
            qk + ((((size_t)b * S_ + s0 + j) * 2 + 1) * H_ + h) * D_ + d4);
        uint4 ku = make_uint4(tf32r(featf(kf.x) * SCALE), tf32r(featf(kf.y) * SCALE),
                              tf32r(featf(kf.z) * SCALE), tf32r(featf(kf.w) * SCALE));
        *reinterpret_cast<uint4*>(&kSu[j * VTS + d4]) = ku;
    }
    CP_WAIT(0);
    __syncthreads();

    const int warp = t >> 5, lane = t & 31;
    const int g = lane >> 2, tq = lane & 3;
    const int d0w = (warp >> 1) * 16;
    const int eh  = warp & 1;

    float acc[4][4];
    #pragma unroll
    for (int n = 0; n < 4; n++)
        #pragma unroll
        for (int p = 0; p < 4; p++) acc[n][p] = 0.f;

    #pragma unroll
    for (int kt = 0; kt < 8; kt++) {
        const int j0 = kt * 8;
        // A = k^T: A[d][j] = kS[j][d]; gather conflict-free (banks 8tq+g)
        uint32_t a0 = kSu[(j0 + tq)     * VTS + d0w + g];
        uint32_t a1 = kSu[(j0 + tq)     * VTS + d0w + g + 8];
        uint32_t a2 = kSu[(j0 + tq + 4) * VTS + d0w + g];
        uint32_t a3 = kSu[(j0 + tq + 4) * VTS + d0w + g + 8];
        #pragma unroll
        for (int nt = 0; nt < 4; nt++) {
            const int e0 = (eh * 4 + nt) * 8;
            uint32_t b0 = tf32r(vS[(j0 + tq)     * VTS + e0 + g]);
            uint32_t b1 = tf32r(vS[(j0 + tq + 4) * VTS + e0 + g]);
            MMA8(acc[nt], a0, a1, a2, a3, b0, b1);
        }
    }

    float* base = g_state + (size_t)(bh * NC_ + c) * (D_ * D_);
    #pragma unroll
    for (int nt = 0; nt < 4; nt++) {
        const int e = (eh * 4 + nt) * 8 + 2 * tq;
        *reinterpret_cast<float2*>(base + (d0w + g)     * D_ + e) =
            make_float2(acc[nt][0], acc[nt][1]);
        *reinterpret_cast<float2*>(base + (d0w + g + 8) * D_ + e) =
            make_float2(acc[nt][2], acc[nt][3]);
    }
}

// ---------------------------------------------------------------------------
// Kernel 2: exclusive prefix over chunks (float4/thread).
// Accumulates in f32; stores RN tf32-rounded bits.  [R15 verbatim]
// ---------------------------------------------------------------------------
__global__ void __launch_bounds__(256) k_prefix() {
    const int el  = blockIdx.x * 256 + threadIdx.x;   // float4 index
    const int bh  = el >> 10;
    const int off = (el & 1023) << 2;
    float* p = g_state + (size_t)bh * NC_ * (D_ * D_) + off;
    float4 run = make_float4(0.f, 0.f, 0.f, 0.f);
    #pragma unroll
    for (int c = 0; c < NC_; c++) {
        float4* q4 = reinterpret_cast<float4*>(p + (size_t)c * (D_ * D_));
        float4 tmp = *q4;
        float4 outq;
        outq.x = __uint_as_float(tf32r(run.x));
        outq.y = __uint_as_float(tf32r(run.y));
        outq.z = __uint_as_float(tf32r(run.z));
        outq.w = __uint_as_float(tf32r(run.w));
        *q4 = outq;
        run.x += tmp.x; run.y += tmp.y; run.z += tmp.z; run.w += tmp.w;
    }
}

// ---------------------------------------------------------------------------
// Kernel 3: out[i][e] = norm_i * ( q@state + causal(q@k^T) @ v )  [R15 verbatim]
// ---------------------------------------------------------------------------
__global__ void __launch_bounds__(256) k_output(const float* __restrict__ qk,
                                                const float* __restrict__ v,
                                                const float* __restrict__ nvec,
                                                const float* __restrict__ offset,
                                                float* __restrict__ out) {
    extern __shared__ float sm[];
    float* qS  = sm;                 // [64][QS_] q (tf32 bits)
    float* kS  = qS + 64 * QS_;      // [64][QS_] k; later scores (stride QS_)
    float* vS  = kS + 64 * QS_;      // [64][VTS] raw f32
    float* stS = vS + 64 * VTS;      // [64][VTS] tf32 bits (pre-rounded)
    float* sS  = kS;                 // scores alias kS
    uint32_t* qSu  = reinterpret_cast<uint32_t*>(qS);
    uint32_t* kSu  = reinterpret_cast<uint32_t*>(kS);
    uint32_t* stSu = reinterpret_cast<uint32_t*>(stS);
    uint32_t* sSu  = reinterpret_cast<uint32_t*>(sS);
    const uint32_t smb = smem_u32(sm);

    const int t  = threadIdx.x;
    const int bh = blockIdx.x / NC_;
    const int c  = blockIdx.x % NC_;
    const int b  = bh / H_, h = bh % H_;
    const int s0 = c * C_;

    const float* stg = g_state + (size_t)(bh * NC_ + c) * (D_ * D_);

    const uint32_t vOff  = (uint32_t)(2 * 64 * QS_);
    const uint32_t stOff = (uint32_t)(2 * 64 * QS_ + 64 * VTS);

    // group 0: state; group 1: v
    #pragma unroll
    for (int r = 0; r < 4; r++) {
        int idx = t + r * 256;
        int row = idx >> 4;
        int d4  = (idx & 15) << 2;
        cp16(smb + (stOff + (uint32_t)(row * VTS + d4)) * 4, stg + row * D_ + d4);
    }
    CP_COMMIT();
    #pragma unroll
    for (int r = 0; r < 4; r++) {
        int idx = t + r * 256;
        int row = idx >> 4;
        int d4  = (idx & 15) << 2;
        cp16(smb + (vOff + (uint32_t)(row * VTS + d4)) * 4,
             v + (((size_t)b * S_ + s0 + row) * H_ + h) * D_ + d4);
    }
    CP_COMMIT();

    // q,k: batch ALL global loads first (MLP=8), then transform+store
    float4 qf[4], kf[4];
    #pragma unroll
    for (int r = 0; r < 4; r++) {
        int idx = t + r * 256;
        int row = idx >> 4;
        int d4  = (idx & 15) << 2;
        size_t s = (size_t)(s0 + row);
        qf[r] = *reinterpret_cast<const float4*>(
            qk + ((((size_t)b * S_ + s) * 2 + 0) * H_ + h) * D_ + d4);
        kf[r] = *reinterpret_cast<const float4*>(
            qk + ((((size_t)b * S_ + s) * 2 + 1) * H_ + h) * D_ + d4);
    }
    #pragma unroll
    for (int r = 0; r < 4; r++) {
        int idx = t + r * 256;
        int row = idx >> 4;
        int d4  = (idx & 15) << 2;
        uint4 qu = make_uint4(tf32r(featf(qf[r].x)), tf32r(featf(qf[r].y)),
                              tf32r(featf(qf[r].z)), tf32r(featf(qf[r].w)));
        *reinterpret_cast<uint4*>(&qSu[row * QS_ + d4]) = qu;
        uint4 ku = make_uint4(tf32r(featf(kf[r].x) * SCALE), tf32r(featf(kf[r].y) * SCALE),
                              tf32r(featf(kf[r].z) * SCALE), tf32r(featf(kf[r].w) * SCALE));
        *reinterpret_cast<uint4*>(&kSu[row * QS_ + d4]) = ku;
    }

    const int warp = t >> 5, lane = t & 31;
    const int g = lane >> 2, tq = lane & 3;
    const int ib = warp >> 1;
    const int eh = warp & 1;
    const int i0 = ib * 16;
    const int ntS = 2 * ib + 2;      // causal j-tiles for this i-block

    const float offh = offset[h];
    const int iA = i0 + g, iB = i0 + g + 8;
    float zA = nvec[((size_t)b * S_ + s0 + iA) * H_ + h] + offh;
    float zB = nvec[((size_t)b * S_ + s0 + iB) * H_ + h] + offh;

    CP_WAIT(0);               // state + v landed
    __syncthreads();

    float dO[4][4];
    float dS[4][4];
    #pragma unroll
    for (int n = 0; n < 4; n++)
        #pragma unroll
        for (int p = 0; p < 4; p++) { dO[n][p] = 0.f; dS[n][p] = 0.f; }

    // Phase 1: out1 = q @ state (own e-tiles); scores = q @ k^T (parity j-tiles)
    #pragma unroll
    for (int kt = 0; kt < 8; kt++) {
        const int d0 = kt * 8;
        uint32_t a0 = qSu[(i0 + g)     * QS_ + d0 + tq];
        uint32_t a1 = qSu[(i0 + g + 8) * QS_ + d0 + tq];
        uint32_t a2 = qSu[(i0 + g)     * QS_ + d0 + tq + 4];
        uint32_t a3 = qSu[(i0 + g + 8) * QS_ + d0 + tq + 4];
        #pragma unroll
        for (int nt = 0; nt < 4; nt++) {
            const int e0 = (eh * 4 + nt) * 8;
            uint32_t b0 = stSu[(d0 + tq)     * VTS + e0 + g];   // pre-rounded bits
            uint32_t b1 = stSu[(d0 + tq + 4) * VTS + e0 + g];
            MMA8(dO[nt], a0, a1, a2, a3, b0, b1);
        }
        #pragma unroll
        for (int nt2 = 0; nt2 < 4; nt2++) {
            const int jt = 2 * nt2 + eh;
            if (jt >= ntS) break;
            const int j0 = jt * 8;
            uint32_t b0 = kSu[(j0 + g) * QS_ + d0 + tq];
            uint32_t b1 = kSu[(j0 + g) * QS_ + d0 + tq + 4];
            MMA8(dS[nt2], a0, a1, a2, a3, b0, b1);
        }
    }

    __syncthreads();           // all reads of kS done; scores may overwrite it

    // Causal mask + store parity score tiles (stride QS_, alias kS)
    #pragma unroll
    for (int nt2 = 0; nt2 < 4; nt2++) {
        const int jt = 2 * nt2 + eh;
        if (jt >= ntS) break;
        const int j = jt * 8 + 2 * tq;
        sSu[iA * QS_ + j]     = tf32r((j     <= iA) ? dS[nt2][0] : 0.f);
        sSu[iA * QS_ + j + 1] = tf32r((j + 1 <= iA) ? dS[nt2][1] : 0.f);
        sSu[iB * QS_ + j]     = tf32r((j     <= iB) ? dS[nt2][2] : 0.f);
        sSu[iB * QS_ + j + 1] = tf32r((j + 1 <= iB) ? dS[nt2][3] : 0.f);
    }
    __syncthreads();           // scores visible to all

    // Phase 2: out += scores @ v (all causal j-tiles, own e-tiles)
    #pragma unroll
    for (int kt = 0; kt < 8; kt++) {
        if (kt >= ntS) break;
        const int j0 = kt * 8;
        uint32_t a0 = sSu[(i0 + g)     * QS_ + j0 + tq];
        uint32_t a1 = sSu[(i0 + g + 8) * QS_ + j0 + tq];
        uint32_t a2 = sSu[(i0 + g)     * QS_ + j0 + tq + 4];
        uint32_t a3 = sSu[(i0 + g + 8) * QS_ + j0 + tq + 4];
        #pragma unroll
        for (int nt = 0; nt < 4; nt++) {
            const int e0 = (eh * 4 + nt) * 8;
            uint32_t b0 = tf32r(vS[(j0 + tq)     * VTS + e0 + g]);
            uint32_t b1 = tf32r(vS[(j0 + tq + 4) * VTS + e0 + g]);
            MMA8(dO[nt], a0, a1, a2, a3, b0, b1);
        }
    }

    // Epilogue: norm scale + direct fragment stores (float2, full sectors)
    float nA = 1.f / (1.f + __expf(zA));
    float nB = 1.f / (1.f + __expf(zB));
    float* opA = out + (((size_t)b * S_ + s0 + iA) * H_ + h) * D_;
    float* opB = out + (((size_t)b * S_ + s0 + iB) * H_ + h) * D_;
    #pragma unroll
    for (int nt = 0; nt < 4; nt++) {
        const int e = (eh * 4 + nt) * 8 + 2 * tq;
        *reinterpret_cast<float2*>(opA + e) =
            make_float2(dO[nt][0] * nA, dO[nt][1] * nA);
        *reinterpret_cast<float2*>(opB + e) =
            make_float2(dO[nt][2] * nB, dO[nt][3] * nB);
    }
}

// ---------------------------------------------------------------------------
extern "C" void kernel_launch(void* const* d_in, const int* in_sizes, int n_in,
                              void* d_out, int out_size) {
    (void)in_sizes; (void)n_in; (void)out_size;
    const float* qk     = (const float*)d_in[0];
    const float* v      = (const float*)d_in[1];
    const float* nvec   = (const float*)d_in[2];
    const float* offset = (const float*)d_in[3];
    float* out = (float*)d_out;

    const int smem1 = (2 * 64 * VTS) * (int)sizeof(float);                 // 36864
    const int smem3 = (2 * 64 * QS_ + 2 * 64 * VTS) * (int)sizeof(float);  // 71680
    cudaFuncSetAttribute(k_chunk_sum, cudaFuncAttributeMaxDynamicSharedMemorySize, smem1);
    cudaFuncSetAttribute(k_output,    cudaFuncAttributeMaxDynamicSharedMemorySize, smem3);

    k_chunk_sum<<<BH_ * NC_, 256, smem1>>>(qk, v);
    k_prefix<<<128, 256>>>();
    k_output<<<BH_ * NC_, 256, smem3>>>(qk, v, nvec, offset, out);
}